// round 2
// baseline (speedup 1.0000x reference)
#include <cuda_runtime.h>
#include <math.h>

#define N_NODES 100000
#define N_EDGES 1600000
#define DIM 128
#define N_LAYERS 3
#define BN_EPS 1e-5f

// ---------------- scratch (static device globals; no allocation) ----------------
__device__ float g_bufA[N_NODES * DIM];
__device__ float g_bufB[N_NODES * DIM];
__device__ int g_cnt[N_NODES];
__device__ int g_cur[N_NODES];
__device__ int g_off[N_NODES + 1];
__device__ int g_srcs[N_EDGES];
__device__ int g_is64;

__device__ __forceinline__ float* bufptr(int s) { return s ? g_bufB : g_bufA; }

// ---------------- edge dtype detection ----------------
// If edge_index is int64, every value < 100000 => odd 32-bit words are all 0.
// If int32, odd words are random node ids (P(all zero) ~ 0).
__global__ void k_detect(const int* __restrict__ e) {
    __shared__ int s;
    if (threadIdx.x == 0) s = 0;
    __syncthreads();
    int v = e[threadIdx.x * 2 + 1];   // first 1024 pairs; both layouts have >= 2048 words
    if (v != 0) atomicOr(&s, 1);
    __syncthreads();
    if (threadIdx.x == 0) g_is64 = (s == 0) ? 1 : 0;
}

__device__ __forceinline__ int edge_idx(const void* e, int part, int i) {
    if (g_is64) return (int)((const long long*)e)[(size_t)part * N_EDGES + i];
    return ((const int*)e)[(size_t)part * N_EDGES + i];
}

// ---------------- CSR build ----------------
__global__ void k_zero() {
    int i = blockIdx.x * blockDim.x + threadIdx.x;
    if (i < N_NODES) { g_cnt[i] = 0; g_cur[i] = 0; }
}

__global__ void k_hist(const void* __restrict__ e) {
    int i = blockIdx.x * blockDim.x + threadIdx.x;
    if (i < N_EDGES) atomicAdd(&g_cnt[edge_idx(e, 1, i)], 1);
}

// single-block exclusive scan over g_cnt -> g_off
__global__ void k_scan() {
    __shared__ int ssum[1024];
    const int T = 1024;
    const int CH = (N_NODES + T - 1) / T;
    int t = threadIdx.x;
    int beg = t * CH;
    int end = beg + CH;
    if (beg > N_NODES) beg = N_NODES;
    if (end > N_NODES) end = N_NODES;
    int s = 0;
    for (int i = beg; i < end; i++) s += g_cnt[i];
    ssum[t] = s;
    __syncthreads();
    for (int o = 1; o < T; o <<= 1) {
        int v = (t >= o) ? ssum[t - o] : 0;
        __syncthreads();
        ssum[t] += v;
        __syncthreads();
    }
    int run = ssum[t] - s;  // exclusive prefix
    for (int i = beg; i < end; i++) {
        g_off[i] = run;
        run += g_cnt[i];
    }
    if (t == T - 1) g_off[N_NODES] = ssum[T - 1];
}

__global__ void k_scatter(const void* __restrict__ e) {
    int i = blockIdx.x * blockDim.x + threadIdx.x;
    if (i < N_EDGES) {
        int d = edge_idx(e, 1, i);
        int p = g_off[d] + atomicAdd(&g_cur[d], 1);
        g_srcs[p] = edge_idx(e, 0, i);
    }
}

// ---------------- aggregation: out[n] = h[n] + sum_{e: dst=n} h[src[e]] ----------------
__global__ void k_agg(const float* __restrict__ X0, int in_sel, int out_sel) {
    int warp = (blockIdx.x * blockDim.x + threadIdx.x) >> 5;
    if (warp >= N_NODES) return;
    int lane = threadIdx.x & 31;
    const float* H = (in_sel < 0) ? X0 : bufptr(in_sel);
    float* O = bufptr(out_sel);
    const float4* H4 = (const float4*)H;
    float4 a = H4[(size_t)warp * 32 + lane];  // self term
    int e0 = g_off[warp], e1 = g_off[warp + 1];
    for (int e = e0; e < e1; e++) {
        int s = g_srcs[e];
        float4 v = __ldg(&H4[(size_t)s * 32 + lane]);
        a.x += v.x; a.y += v.y; a.z += v.z; a.w += v.w;
    }
    ((float4*)O)[(size_t)warp * 32 + lane] = a;
}

// ---------------- fused GEMM + epilogue ----------------
typedef unsigned long long u64;

__device__ __forceinline__ void ffma2(u64& d, u64 a, u64 b) {
    asm("fma.rn.f32x2 %0, %1, %2, %0;" : "+l"(d) : "l"(a), "l"(b));
}
__device__ __forceinline__ u64 pack2(float x, float y) {
    u64 r; asm("mov.b64 %0, {%1, %2};" : "=l"(r) : "f"(x), "f"(y)); return r;
}
__device__ __forceinline__ float2 unpack2(u64 v) {
    float2 r; asm("mov.b64 {%0, %1}, %2;" : "=f"(r.x), "=f"(r.y) : "l"(v)); return r;
}

#define XS_STRIDE 132
#define MLP_ROWS 64
#define SMEM_SZ ((DIM * DIM + MLP_ROWS * XS_STRIDE) * 4)

// MODE 0: out = relu((x@W + b - mean) * gamma*rsqrt(var+eps) + beta)
// MODE 1: out = relu(x@W + b)
template <int MODE>
__global__ void __launch_bounds__(256, 2)
k_mlp(int in_sel, int out_sel, const float* __restrict__ W,
      const float* __restrict__ b, const float* __restrict__ gamma,
      const float* __restrict__ beta, const float* __restrict__ mean,
      const float* __restrict__ var) {
    extern __shared__ float sm[];
    float* Ws = sm;               // 128x128 (row = k, col = c)
    float* Xs = sm + DIM * DIM;   // 64 rows, stride 132
    const float* X = bufptr(in_sel);
    float* Y = bufptr(out_sel);
    int tid = threadIdx.x;
    int row0 = blockIdx.x * MLP_ROWS;

    // stage W
    const float4* W4 = (const float4*)W;
    float4* Ws4 = (float4*)Ws;
    #pragma unroll
    for (int i = tid; i < DIM * DIM / 4; i += 256) Ws4[i] = W4[i];
    // stage X tile
    const float4* X4 = (const float4*)X;
    for (int i = tid; i < MLP_ROWS * 32; i += 256) {
        int r = i >> 5, c = i & 31;
        float4 v = make_float4(0.f, 0.f, 0.f, 0.f);
        if (row0 + r < N_NODES) v = X4[(size_t)(row0 + r) * 32 + c];
        *(float4*)&Xs[r * XS_STRIDE + c * 4] = v;
    }
    __syncthreads();

    int tx = tid & 15, ty = tid >> 4;   // thread tile: 4 rows x 8 cols
    u64 acc[4][4];
    #pragma unroll
    for (int i = 0; i < 4; i++)
        #pragma unroll
        for (int j = 0; j < 4; j++) acc[i][j] = 0ull;

    const float* xrow = &Xs[(ty * 4) * XS_STRIDE];
    const int c0 = tx * 8;

    #pragma unroll 2
    for (int k = 0; k < DIM; k += 4) {
        float4 xa[4];
        #pragma unroll
        for (int i = 0; i < 4; i++)
            xa[i] = *(const float4*)&xrow[i * XS_STRIDE + k];
        #pragma unroll
        for (int kk = 0; kk < 4; kk++) {
            float4 w0 = *(const float4*)&Ws[(k + kk) * DIM + c0];
            float4 w1 = *(const float4*)&Ws[(k + kk) * DIM + c0 + 4];
            u64 w01a = pack2(w0.x, w0.y), w01b = pack2(w0.z, w0.w);
            u64 w23a = pack2(w1.x, w1.y), w23b = pack2(w1.z, w1.w);
            #pragma unroll
            for (int i = 0; i < 4; i++) {
                float a = (kk == 0) ? xa[i].x : (kk == 1) ? xa[i].y
                        : (kk == 2) ? xa[i].z : xa[i].w;
                u64 aa = pack2(a, a);
                ffma2(acc[i][0], aa, w01a);
                ffma2(acc[i][1], aa, w01b);
                ffma2(acc[i][2], aa, w23a);
                ffma2(acc[i][3], aa, w23b);
            }
        }
    }

    // epilogue: per-column scale/shift
    float scale[8], shift[8];
    #pragma unroll
    for (int j = 0; j < 8; j++) {
        int c = c0 + j;
        if (MODE == 0) {
            float s = gamma[c] * rsqrtf(var[c] + BN_EPS);
            scale[j] = s;
            shift[j] = (b[c] - mean[c]) * s + beta[c];
        } else {
            scale[j] = 1.f;
            shift[j] = b[c];
        }
    }
    #pragma unroll
    for (int i = 0; i < 4; i++) {
        int r = row0 + ty * 4 + i;
        if (r >= N_NODES) continue;
        float o[8];
        #pragma unroll
        for (int j = 0; j < 4; j++) {
            float2 v = unpack2(acc[i][j]);
            o[j * 2] = v.x; o[j * 2 + 1] = v.y;
        }
        #pragma unroll
        for (int j = 0; j < 8; j++) {
            float y = o[j] * scale[j] + shift[j];
            o[j] = y > 0.f ? y : 0.f;
        }
        float4* Yp = (float4*)&Y[(size_t)r * DIM + c0];
        Yp[0] = make_float4(o[0], o[1], o[2], o[3]);
        Yp[1] = make_float4(o[4], o[5], o[6], o[7]);
    }
}

// ---------------- log-softmax (warp per row) ----------------
__global__ void k_lsm(int in_sel, float* __restrict__ Y) {
    int warp = (blockIdx.x * blockDim.x + threadIdx.x) >> 5;
    if (warp >= N_NODES) return;
    int lane = threadIdx.x & 31;
    const float* X = bufptr(in_sel);
    float4 v = ((const float4*)X)[(size_t)warp * 32 + lane];
    float m = fmaxf(fmaxf(v.x, v.y), fmaxf(v.z, v.w));
    #pragma unroll
    for (int o = 16; o; o >>= 1) m = fmaxf(m, __shfl_xor_sync(0xffffffffu, m, o));
    float s = expf(v.x - m) + expf(v.y - m) + expf(v.z - m) + expf(v.w - m);
    #pragma unroll
    for (int o = 16; o; o >>= 1) s += __shfl_xor_sync(0xffffffffu, s, o);
    float ls = m + logf(s);
    ((float4*)Y)[(size_t)warp * 32 + lane] =
        make_float4(v.x - ls, v.y - ls, v.z - ls, v.w - ls);
}

// ---------------- launch ----------------
extern "C" void kernel_launch(void* const* d_in, const int* in_sizes, int n_in,
                              void* d_out, int out_size) {
    const float* x     = (const float*)d_in[0];
    const void* ei     = d_in[1];
    const float* W1    = (const float*)d_in[2];
    const float* b1    = (const float*)d_in[3];
    const float* gamma = (const float*)d_in[4];
    const float* beta  = (const float*)d_in[5];
    const float* rmean = (const float*)d_in[6];
    const float* rvar  = (const float*)d_in[7];
    const float* W2    = (const float*)d_in[8];
    const float* b2    = (const float*)d_in[9];
    float* out = (float*)d_out;

    cudaFuncSetAttribute(k_mlp<0>, cudaFuncAttributeMaxDynamicSharedMemorySize, SMEM_SZ);
    cudaFuncSetAttribute(k_mlp<1>, cudaFuncAttributeMaxDynamicSharedMemorySize, SMEM_SZ);

    // CSR build
    k_detect<<<1, 1024>>>((const int*)ei);
    k_zero<<<(N_NODES + 255) / 256, 256>>>();
    k_hist<<<(N_EDGES + 255) / 256, 256>>>(ei);
    k_scan<<<1, 1024>>>();
    k_scatter<<<(N_EDGES + 255) / 256, 256>>>(ei);

    const int AGG_BLOCKS = (N_NODES * 32 + 255) / 256;
    const int MLP_BLOCKS = (N_NODES + MLP_ROWS - 1) / MLP_ROWS;

    // dataflow: agg(x->A) mlp0(A->B) mlp1(B->A) | agg(A->B) mlp0(B->A) mlp1(A->B)
    //           | agg(B->A) mlp0(A->B) mlp1(B->A) | lsm(A->out)
    int in_sel = -1;   // x
    int t = 0;         // next write target: A
    for (int l = 0; l < N_LAYERS; l++) {
        k_agg<<<AGG_BLOCKS, 256>>>(x, in_sel, t);
        k_mlp<0><<<MLP_BLOCKS, 256, SMEM_SZ>>>(t, t ^ 1, W1 + (size_t)l * DIM * DIM,
                                               b1 + l * DIM, gamma + l * DIM,
                                               beta + l * DIM, rmean + l * DIM,
                                               rvar + l * DIM);
        k_mlp<1><<<MLP_BLOCKS, 256, SMEM_SZ>>>(t ^ 1, t, W2 + (size_t)l * DIM * DIM,
                                               b2 + l * DIM, b2 + l * DIM,
                                               b2 + l * DIM, b2 + l * DIM,
                                               b2 + l * DIM);
        in_sel = t;
        t ^= 1;
    }
    k_lsm<<<AGG_BLOCKS, 256>>>(in_sel, out);
}

// round 5
// speedup vs baseline: 1.6338x; 1.6338x over previous
#include <cuda_runtime.h>
#include <cuda_bf16.h>
#include <stdint.h>
#include <math.h>

#define N_NODES 100000
#define N_EDGES 1600000
#define DIM 128
#define N_LAYERS 3
#define BN_EPS 1e-5f

// ---------------- scratch (static device globals; no allocation) ----------------
__device__ float g_bufA[N_NODES * DIM];
__device__ float g_bufB[N_NODES * DIM];
__device__ int g_cnt[N_NODES];
__device__ int g_cur[N_NODES];
__device__ int g_off[N_NODES + 1];
__device__ int g_srcs[N_EDGES];
__device__ int g_is64;
__device__ int g_bsum[128];
__device__ int g_bsumx[128];
// Pre-built padded SMEM image of B = W^T in bf16 hi/lo planes:
// per matrix: plane(hi)[128 rows(n) x 136 bf16 (272B, k-major)], plane(lo) same.
#define WIMG_PLANE 34816   // 128*272
#define WIMG_MAT   69632   // 2 planes
__device__ unsigned char g_Wimg[6 * WIMG_MAT];

__device__ __forceinline__ float* bufptr(int s) { return s ? g_bufB : g_bufA; }

__device__ __forceinline__ uint32_t smem_u32(const void* p) {
    uint32_t a;
    asm("{ .reg .u64 t; cvta.to.shared.u64 t, %1; cvt.u32.u64 %0, t; }" : "=r"(a) : "l"(p));
    return a;
}

// ---------------- edge dtype detection ----------------
__global__ void k_detect(const int* __restrict__ e) {
    __shared__ int s;
    if (threadIdx.x == 0) s = 0;
    __syncthreads();
    int v = e[threadIdx.x * 2 + 1];
    if (v != 0) atomicOr(&s, 1);
    __syncthreads();
    if (threadIdx.x == 0) g_is64 = (s == 0) ? 1 : 0;
}
__device__ __forceinline__ int edge_idx(const void* e, int part, int i) {
    if (g_is64) return (int)((const long long*)e)[(size_t)part * N_EDGES + i];
    return ((const int*)e)[(size_t)part * N_EDGES + i];
}

// ---------------- CSR build ----------------
__global__ void k_zero() {
    int i = blockIdx.x * blockDim.x + threadIdx.x;
    if (i < N_NODES) { g_cnt[i] = 0; g_cur[i] = 0; }
}
__global__ void k_hist(const void* __restrict__ e) {
    int i = blockIdx.x * blockDim.x + threadIdx.x;
    if (i < N_EDGES) atomicAdd(&g_cnt[edge_idx(e, 1, i)], 1);
}
// hierarchical scan
__global__ void k_scanA() {
    __shared__ int sh[1024];
    int t = threadIdx.x, i = blockIdx.x * 1024 + t;
    int v = (i < N_NODES) ? g_cnt[i] : 0;
    sh[t] = v; __syncthreads();
    for (int o = 1; o < 1024; o <<= 1) {
        int u = (t >= o) ? sh[t - o] : 0;
        __syncthreads(); sh[t] += u; __syncthreads();
    }
    if (i < N_NODES) g_off[i] = sh[t] - v;
    if (t == 1023) g_bsum[blockIdx.x] = sh[t];
}
__global__ void k_scanB() {
    __shared__ int sh[128];
    int t = threadIdx.x;
    int v = (t < 98) ? g_bsum[t] : 0;
    sh[t] = v; __syncthreads();
    for (int o = 1; o < 128; o <<= 1) {
        int u = (t >= o) ? sh[t - o] : 0;
        __syncthreads(); sh[t] += u; __syncthreads();
    }
    g_bsumx[t] = sh[t] - v;
}
__global__ void k_scanC() {
    int t = threadIdx.x, i = blockIdx.x * 1024 + t;
    if (i < N_NODES) g_off[i] += g_bsumx[blockIdx.x];
    if (i == 0) g_off[N_NODES] = N_EDGES;
}
__global__ void k_scatter(const void* __restrict__ e) {
    int i = blockIdx.x * blockDim.x + threadIdx.x;
    if (i < N_EDGES) {
        int d = edge_idx(e, 1, i);
        int p = g_off[d] + atomicAdd(&g_cur[d], 1);
        g_srcs[p] = edge_idx(e, 0, i);
    }
}

// ---------------- aggregation ----------------
__global__ void k_agg(const float* __restrict__ X0, int in_sel, int out_sel) {
    int warp = (blockIdx.x * blockDim.x + threadIdx.x) >> 5;
    if (warp >= N_NODES) return;
    int lane = threadIdx.x & 31;
    const float* H = (in_sel < 0) ? X0 : bufptr(in_sel);
    float* O = bufptr(out_sel);
    const float4* H4 = (const float4*)H;
    float4 a = H4[(size_t)warp * 32 + lane];
    int e0 = g_off[warp], e1 = g_off[warp + 1];
    for (int e = e0; e < e1; e++) {
        int s = g_srcs[e];
        float4 v = __ldg(&H4[(size_t)s * 32 + lane]);
        a.x += v.x; a.y += v.y; a.z += v.z; a.w += v.w;
    }
    ((float4*)O)[(size_t)warp * 32 + lane] = a;
}

// ---------------- weight image prep (padded bf16 hi/lo B image) ----------------
__global__ void k_wimg(const float* __restrict__ W1, const float* __restrict__ W2) {
    int idx = blockIdx.x * blockDim.x + threadIdx.x;  // 6 * 128 * 64
    if (idx >= 6 * 128 * 64) return;
    int mat = idx >> 13;           // /8192
    int rem = idx & 8191;
    int n = rem >> 6;              // output column = B row
    int kp = rem & 63;             // k pair
    int k = kp * 2;
    int layer = mat >> 1, which = mat & 1;
    const float* Wsrc = (which ? W2 : W1) + (size_t)layer * DIM * DIM;
    float w0 = Wsrc[k * DIM + n];
    float w1 = Wsrc[(k + 1) * DIM + n];
    __nv_bfloat16 h0 = __float2bfloat16(w0);
    __nv_bfloat16 h1 = __float2bfloat16(w1);
    __nv_bfloat16 l0 = __float2bfloat16(w0 - __bfloat162float(h0));
    __nv_bfloat16 l1 = __float2bfloat16(w1 - __bfloat162float(h1));
    __nv_bfloat162 hp; hp.x = h0; hp.y = h1;
    __nv_bfloat162 lp; lp.x = l0; lp.y = l1;
    int off = mat * WIMG_MAT + n * 272 + kp * 4;
    *(uint32_t*)&g_Wimg[off] = *(uint32_t*)&hp;
    *(uint32_t*)&g_Wimg[off + WIMG_PLANE] = *(uint32_t*)&lp;
}

// ---------------- HMMA fused GEMM + epilogue ----------------
// Y[128 x 128] = X @ W via 2-term bf16 split (3 passes), mma.sync m16n8k16.
// SMEM: [0..512) scale, [512..1024) shift, A planes @1024, B planes @70656.
#define A_OFF 1024
#define B_OFF (A_OFF + WIMG_MAT)
#define TC_SMEM (B_OFF + WIMG_MAT)

__device__ __forceinline__ void ldsm4(uint32_t addr, uint32_t* r) {
    asm volatile("ldmatrix.sync.aligned.m8n8.x4.shared.b16 {%0,%1,%2,%3}, [%4];"
                 : "=r"(r[0]), "=r"(r[1]), "=r"(r[2]), "=r"(r[3]) : "r"(addr));
}
__device__ __forceinline__ void mma16816(float* c, const uint32_t* a,
                                         uint32_t b0, uint32_t b1) {
    asm volatile("mma.sync.aligned.m16n8k16.row.col.f32.bf16.bf16.f32 "
                 "{%0,%1,%2,%3}, {%4,%5,%6,%7}, {%8,%9}, {%0,%1,%2,%3};"
                 : "+f"(c[0]), "+f"(c[1]), "+f"(c[2]), "+f"(c[3])
                 : "r"(a[0]), "r"(a[1]), "r"(a[2]), "r"(a[3]), "r"(b0), "r"(b1));
}

template <int MODE>
__global__ void __launch_bounds__(512, 1)
k_mlp_tc(int in_sel, int out_sel, int mat,
         const float* __restrict__ b, const float* __restrict__ gamma,
         const float* __restrict__ beta, const float* __restrict__ mean,
         const float* __restrict__ var) {
    extern __shared__ char smem[];
    uint32_t sbase = smem_u32(smem);
    int tid = threadIdx.x;
    int wid = tid >> 5, lane = tid & 31;
    int row0 = blockIdx.x * 128;
    const float* X = bufptr(in_sel);
    float* Y = bufptr(out_sel);

    // header: per-column scale/shift
    if (tid < 128) {
        int c = tid;
        float sc, sh;
        if (MODE == 0) {
            float s = gamma[c] * rsqrtf(var[c] + BN_EPS);
            sc = s; sh = (b[c] - mean[c]) * s + beta[c];
        } else { sc = 1.f; sh = b[c]; }
        *(float*)(smem + c * 4) = sc;
        *(float*)(smem + 512 + c * 4) = sh;
    }

    // B: flat copy of prebuilt padded image (69632 B)
    {
        const float4* src = (const float4*)(g_Wimg + (size_t)mat * WIMG_MAT);
        float4* dst = (float4*)(smem + B_OFF);
        for (int i = tid; i < WIMG_MAT / 16; i += 512) dst[i] = src[i];
    }

    // A: 4 threads per row; fp32 -> bf16 hi/lo into padded planes
    {
        int r = tid >> 2, q = tid & 3;
        bool valid = (row0 + r) < N_NODES;
        const float4* xr = (const float4*)X + (size_t)(row0 + r) * 32 + q * 8;
        char* arow = smem + A_OFF + r * 272;
        #pragma unroll
        for (int p = 0; p < 8; p++) {
            float4 v = valid ? __ldg(&xr[p]) : make_float4(0.f, 0.f, 0.f, 0.f);
            int kb = (q * 32 + p * 4) * 2;   // byte offset of k within row
            __nv_bfloat16 hx = __float2bfloat16(v.x), hy = __float2bfloat16(v.y);
            __nv_bfloat16 hz = __float2bfloat16(v.z), hw = __float2bfloat16(v.w);
            __nv_bfloat162 h01; h01.x = hx; h01.y = hy;
            __nv_bfloat162 h23; h23.x = hz; h23.y = hw;
            __nv_bfloat162 l01, l23;
            l01.x = __float2bfloat16(v.x - __bfloat162float(hx));
            l01.y = __float2bfloat16(v.y - __bfloat162float(hy));
            l23.x = __float2bfloat16(v.z - __bfloat162float(hz));
            l23.y = __float2bfloat16(v.w - __bfloat162float(hw));
            *(uint32_t*)(arow + kb)     = *(uint32_t*)&h01;
            *(uint32_t*)(arow + kb + 4) = *(uint32_t*)&h23;
            *(uint32_t*)(arow + WIMG_PLANE + kb)     = *(uint32_t*)&l01;
            *(uint32_t*)(arow + WIMG_PLANE + kb + 4) = *(uint32_t*)&l23;
        }
    }
    __syncthreads();

    // warp grid 4(m) x 4(n); warp tile 32m x 32n
    int wm = wid & 3, wn = wid >> 2;
    float acc[2][4][4];
    #pragma unroll
    for (int mt = 0; mt < 2; mt++)
        #pragma unroll
        for (int nt = 0; nt < 4; nt++)
            #pragma unroll
            for (int j = 0; j < 4; j++) acc[mt][nt][j] = 0.f;

    // ldmatrix lane base addresses
    uint32_t addrA[2], addrB[2];
    #pragma unroll
    for (int mt = 0; mt < 2; mt++)
        addrA[mt] = sbase + A_OFF + (wm * 32 + mt * 16 + (lane & 15)) * 272
                    + (lane >> 4) * 16;
    #pragma unroll
    for (int ntp = 0; ntp < 2; ntp++) {
        int quad = lane >> 3;
        int n = wn * 32 + ntp * 16 + (quad >> 1) * 8 + (lane & 7);
        addrB[ntp] = sbase + B_OFF + n * 272 + (quad & 1) * 16;
    }

    // 3 passes: (hi,hi) (hi,lo) (lo,hi)
    #pragma unroll
    for (int pass = 0; pass < 3; pass++) {
        uint32_t aOff = (pass == 2) ? WIMG_PLANE : 0;
        uint32_t bOff = (pass == 1) ? WIMG_PLANE : 0;
        #pragma unroll
        for (int ks = 0; ks < 8; ks++) {
            uint32_t ko = ks * 32;
            uint32_t afr[2][4], bfr[2][4];
            #pragma unroll
            for (int mt = 0; mt < 2; mt++) ldsm4(addrA[mt] + aOff + ko, afr[mt]);
            #pragma unroll
            for (int ntp = 0; ntp < 2; ntp++) ldsm4(addrB[ntp] + bOff + ko, bfr[ntp]);
            #pragma unroll
            for (int mt = 0; mt < 2; mt++)
                #pragma unroll
                for (int nt = 0; nt < 4; nt++)
                    mma16816(acc[mt][nt], afr[mt],
                             bfr[nt >> 1][(nt & 1) * 2], bfr[nt >> 1][(nt & 1) * 2 + 1]);
        }
    }

    // epilogue: scale/shift/relu, direct stores (float2 per fragment row)
    #pragma unroll
    for (int mt = 0; mt < 2; mt++) {
        #pragma unroll
        for (int nt = 0; nt < 4; nt++) {
            int n = wn * 32 + nt * 8 + (lane & 3) * 2;
            float2 sc = *(float2*)(smem + n * 4);
            float2 sh = *(float2*)(smem + 512 + n * 4);
            int r1 = row0 + wm * 32 + mt * 16 + (lane >> 2);
            int r2 = r1 + 8;
            float* c = acc[mt][nt];
            if (r1 < N_NODES) {
                float2 o;
                o.x = fmaxf(fmaf(c[0], sc.x, sh.x), 0.f);
                o.y = fmaxf(fmaf(c[1], sc.y, sh.y), 0.f);
                *(float2*)(Y + (size_t)r1 * DIM + n) = o;
            }
            if (r2 < N_NODES) {
                float2 o;
                o.x = fmaxf(fmaf(c[2], sc.x, sh.x), 0.f);
                o.y = fmaxf(fmaf(c[3], sc.y, sh.y), 0.f);
                *(float2*)(Y + (size_t)r2 * DIM + n) = o;
            }
        }
    }
}

// ---------------- log-softmax (warp per row) ----------------
__global__ void k_lsm(int in_sel, float* __restrict__ Y) {
    int warp = (blockIdx.x * blockDim.x + threadIdx.x) >> 5;
    if (warp >= N_NODES) return;
    int lane = threadIdx.x & 31;
    const float* X = bufptr(in_sel);
    float4 v = ((const float4*)X)[(size_t)warp * 32 + lane];
    float m = fmaxf(fmaxf(v.x, v.y), fmaxf(v.z, v.w));
    #pragma unroll
    for (int o = 16; o; o >>= 1) m = fmaxf(m, __shfl_xor_sync(0xffffffffu, m, o));
    float s = expf(v.x - m) + expf(v.y - m) + expf(v.z - m) + expf(v.w - m);
    #pragma unroll
    for (int o = 16; o; o >>= 1) s += __shfl_xor_sync(0xffffffffu, s, o);
    float ls = m + logf(s);
    ((float4*)Y)[(size_t)warp * 32 + lane] =
        make_float4(v.x - ls, v.y - ls, v.z - ls, v.w - ls);
}

// ---------------- launch ----------------
extern "C" void kernel_launch(void* const* d_in, const int* in_sizes, int n_in,
                              void* d_out, int out_size) {
    const float* x     = (const float*)d_in[0];
    const void* ei     = d_in[1];
    const float* W1    = (const float*)d_in[2];
    const float* b1    = (const float*)d_in[3];
    const float* gamma = (const float*)d_in[4];
    const float* beta  = (const float*)d_in[5];
    const float* rmean = (const float*)d_in[6];
    const float* rvar  = (const float*)d_in[7];
    const float* W2    = (const float*)d_in[8];
    const float* b2    = (const float*)d_in[9];
    float* out = (float*)d_out;

    cudaFuncSetAttribute(k_mlp_tc<0>, cudaFuncAttributeMaxDynamicSharedMemorySize, TC_SMEM);
    cudaFuncSetAttribute(k_mlp_tc<1>, cudaFuncAttributeMaxDynamicSharedMemorySize, TC_SMEM);

    // CSR build + weight images
    k_detect<<<1, 1024>>>((const int*)ei);
    k_zero<<<(N_NODES + 255) / 256, 256>>>();
    k_wimg<<<(6 * 128 * 64 + 255) / 256, 256>>>(W1, W2);
    k_hist<<<(N_EDGES + 255) / 256, 256>>>(ei);
    k_scanA<<<98, 1024>>>();
    k_scanB<<<1, 128>>>();
    k_scanC<<<98, 1024>>>();
    k_scatter<<<(N_EDGES + 255) / 256, 256>>>(ei);

    const int AGG_BLOCKS = (N_NODES * 32 + 255) / 256;
    const int MLP_BLOCKS = (N_NODES + 127) / 128;

    int in_sel = -1;   // x
    int t = 0;
    for (int l = 0; l < N_LAYERS; l++) {
        k_agg<<<AGG_BLOCKS, 256>>>(x, in_sel, t);
        k_mlp_tc<0><<<MLP_BLOCKS, 512, TC_SMEM>>>(t, t ^ 1, l * 2 + 0,
                                                  b1 + l * DIM, gamma + l * DIM,
                                                  beta + l * DIM, rmean + l * DIM,
                                                  rvar + l * DIM);
        k_mlp_tc<1><<<MLP_BLOCKS, 512, TC_SMEM>>>(t ^ 1, t, l * 2 + 1,
                                                  b2 + l * DIM, b2 + l * DIM,
                                                  b2 + l * DIM, b2 + l * DIM,
                                                  b2 + l * DIM);
        in_sel = t;
        t ^= 1;
    }
    k_lsm<<<AGG_BLOCKS, 256>>>(in_sel, out);
}

// round 7
// speedup vs baseline: 1.9043x; 1.1656x over previous
#include <cuda_runtime.h>
#include <cuda_bf16.h>
#include <cuda_fp16.h>
#include <stdint.h>
#include <math.h>

#define N_NODES 100000
#define N_EDGES 1600000
#define DIM 128
#define N_LAYERS 3
#define BN_EPS 1e-5f

// ---------------- scratch (static device globals; no allocation) ----------------
__device__ float g_bufA[N_NODES * DIM];
__device__ float g_bufB[N_NODES * DIM];
__device__ __half2 g_bufH[N_NODES * DIM / 2];   // fp16 shadow for gathers
__device__ int g_cnt[N_NODES];
__device__ int g_cur[N_NODES];
__device__ int g_off[N_NODES + 1];
__device__ int g_srcs[N_EDGES];
__device__ int g_is64;
__device__ int g_bsum[128];
__device__ int g_bsumx[128];
// Pre-built padded SMEM image of B = W^T in bf16 hi/lo planes:
// per matrix: plane(hi)[128 rows(n) x 136 bf16 (272B, k-major)], plane(lo) same.
#define WIMG_PLANE 34816   // 128*272
#define WIMG_MAT   69632   // 2 planes
__device__ unsigned char g_Wimg[6 * WIMG_MAT];

__device__ __forceinline__ float* bufptr(int s) { return s ? g_bufB : g_bufA; }

__device__ __forceinline__ uint32_t smem_u32(const void* p) {
    uint32_t a;
    asm("{ .reg .u64 t; cvta.to.shared.u64 t, %1; cvt.u32.u64 %0, t; }" : "=r"(a) : "l"(p));
    return a;
}

// ---------------- edge dtype detection ----------------
__global__ void k_detect(const int* __restrict__ e) {
    __shared__ int s;
    if (threadIdx.x == 0) s = 0;
    __syncthreads();
    int v = e[threadIdx.x * 2 + 1];
    if (v != 0) atomicOr(&s, 1);
    __syncthreads();
    if (threadIdx.x == 0) g_is64 = (s == 0) ? 1 : 0;
}
__device__ __forceinline__ int edge_idx(const void* e, int part, int i) {
    if (g_is64) return (int)((const long long*)e)[(size_t)part * N_EDGES + i];
    return ((const int*)e)[(size_t)part * N_EDGES + i];
}

// ---------------- CSR build ----------------
__global__ void k_zero() {
    int i = blockIdx.x * blockDim.x + threadIdx.x;
    if (i < N_NODES) { g_cnt[i] = 0; g_cur[i] = 0; }
}
__global__ void k_hist(const void* __restrict__ e) {
    int i = blockIdx.x * blockDim.x + threadIdx.x;
    if (i < N_EDGES) atomicAdd(&g_cnt[edge_idx(e, 1, i)], 1);
}
__global__ void k_scanA() {
    __shared__ int sh[1024];
    int t = threadIdx.x, i = blockIdx.x * 1024 + t;
    int v = (i < N_NODES) ? g_cnt[i] : 0;
    sh[t] = v; __syncthreads();
    for (int o = 1; o < 1024; o <<= 1) {
        int u = (t >= o) ? sh[t - o] : 0;
        __syncthreads(); sh[t] += u; __syncthreads();
    }
    if (i < N_NODES) g_off[i] = sh[t] - v;
    if (t == 1023) g_bsum[blockIdx.x] = sh[t];
}
__global__ void k_scanB() {
    __shared__ int sh[128];
    int t = threadIdx.x;
    int v = (t < 98) ? g_bsum[t] : 0;
    sh[t] = v; __syncthreads();
    for (int o = 1; o < 128; o <<= 1) {
        int u = (t >= o) ? sh[t - o] : 0;
        __syncthreads(); sh[t] += u; __syncthreads();
    }
    g_bsumx[t] = sh[t] - v;
}
__global__ void k_scanC() {
    int t = threadIdx.x, i = blockIdx.x * 1024 + t;
    if (i < N_NODES) g_off[i] += g_bsumx[blockIdx.x];
    if (i == 0) g_off[N_NODES] = N_EDGES;
}
__global__ void k_scatter(const void* __restrict__ e) {
    int i = blockIdx.x * blockDim.x + threadIdx.x;
    if (i < N_EDGES) {
        int d = edge_idx(e, 1, i);
        int p = g_off[d] + atomicAdd(&g_cur[d], 1);
        g_srcs[p] = edge_idx(e, 0, i);
    }
}

// ---------------- fp16 shadow of x (layer 0 gather input) ----------------
__global__ void k_tohalf(const float* __restrict__ X) {
    int i = blockIdx.x * blockDim.x + threadIdx.x;   // over N_NODES*32 float4s
    if (i >= N_NODES * 32) return;
    float4 v = ((const float4*)X)[i];
    g_bufH[i * 2]     = __floats2half2_rn(v.x, v.y);
    g_bufH[i * 2 + 1] = __floats2half2_rn(v.z, v.w);
}

// ---------------- aggregation: self fp32 + fp16 neighbor gather ----------------
__global__ void k_agg(const float* __restrict__ X0, int in_sel, int out_sel) {
    int warp = (blockIdx.x * blockDim.x + threadIdx.x) >> 5;
    if (warp >= N_NODES) return;
    int lane = threadIdx.x & 31;
    const float* H = (in_sel < 0) ? X0 : bufptr(in_sel);
    float* O = bufptr(out_sel);
    float4 a = ((const float4*)H)[(size_t)warp * 32 + lane];
    const uint2* H2 = (const uint2*)g_bufH;
    int e0 = g_off[warp], e1 = g_off[warp + 1];
    for (int e = e0; e < e1; e++) {
        int s = g_srcs[e];
        uint2 u = __ldg(&H2[(size_t)s * 32 + lane]);
        float2 f0 = __half22float2(*(__half2*)&u.x);
        float2 f1 = __half22float2(*(__half2*)&u.y);
        a.x += f0.x; a.y += f0.y; a.z += f1.x; a.w += f1.y;
    }
    ((float4*)O)[(size_t)warp * 32 + lane] = a;
}

// ---------------- weight image prep (padded bf16 hi/lo B image) ----------------
__global__ void k_wimg(const float* __restrict__ W1, const float* __restrict__ W2) {
    int idx = blockIdx.x * blockDim.x + threadIdx.x;  // 6 * 128 * 64
    if (idx >= 6 * 128 * 64) return;
    int mat = idx >> 13;
    int rem = idx & 8191;
    int n = rem >> 6;              // output column = B row
    int kp = rem & 63;             // k pair
    int k = kp * 2;
    int layer = mat >> 1, which = mat & 1;
    const float* Wsrc = (which ? W2 : W1) + (size_t)layer * DIM * DIM;
    float w0 = Wsrc[k * DIM + n];
    float w1 = Wsrc[(k + 1) * DIM + n];
    __nv_bfloat16 h0 = __float2bfloat16(w0);
    __nv_bfloat16 h1 = __float2bfloat16(w1);
    __nv_bfloat16 l0 = __float2bfloat16(w0 - __bfloat162float(h0));
    __nv_bfloat16 l1 = __float2bfloat16(w1 - __bfloat162float(h1));
    __nv_bfloat162 hp; hp.x = h0; hp.y = h1;
    __nv_bfloat162 lp; lp.x = l0; lp.y = l1;
    int off = mat * WIMG_MAT + n * 272 + kp * 4;
    *(uint32_t*)&g_Wimg[off] = *(uint32_t*)&hp;
    *(uint32_t*)&g_Wimg[off + WIMG_PLANE] = *(uint32_t*)&lp;
}

// ---------------- fused 2-GEMM MLP (HMMA, 2-term bf16 split) ----------------
// Z = relu(BN(X@W1+b1)); Y = relu(Z@W2+b2). Z lives only in SMEM.
// SMEM: [0..512) scale1, [512..1024) shift1, [1024..1536) shift2,
//       A/Z planes @A_OFF, W1 planes @B1_OFF, W2 planes @B2_OFF.
#define A_OFF 1536
#define B1_OFF (A_OFF + WIMG_MAT)
#define B2_OFF (B1_OFF + WIMG_MAT)
#define TC_SMEM (B2_OFF + WIMG_MAT)

__device__ __forceinline__ void ldsm4(uint32_t addr, uint32_t* r) {
    asm volatile("ldmatrix.sync.aligned.m8n8.x4.shared.b16 {%0,%1,%2,%3}, [%4];"
                 : "=r"(r[0]), "=r"(r[1]), "=r"(r[2]), "=r"(r[3]) : "r"(addr));
}
__device__ __forceinline__ void mma16816(float* c, const uint32_t* a,
                                         uint32_t b0, uint32_t b1) {
    asm volatile("mma.sync.aligned.m16n8k16.row.col.f32.bf16.bf16.f32 "
                 "{%0,%1,%2,%3}, {%4,%5,%6,%7}, {%8,%9}, {%0,%1,%2,%3};"
                 : "+f"(c[0]), "+f"(c[1]), "+f"(c[2]), "+f"(c[3])
                 : "r"(a[0]), "r"(a[1]), "r"(a[2]), "r"(a[3]), "r"(b0), "r"(b1));
}
__device__ __forceinline__ uint32_t bf16pack(float a, float b) {
    __nv_bfloat162 p; p.x = __float2bfloat16(a); p.y = __float2bfloat16(b);
    return *(uint32_t*)&p;
}

__global__ void __launch_bounds__(512, 1)
k_mlp_fused(int in_sel, int out_sel, int mat1, int mat2, int write_half,
            const float* __restrict__ b1, const float* __restrict__ gamma,
            const float* __restrict__ beta, const float* __restrict__ mean,
            const float* __restrict__ var, const float* __restrict__ b2) {
    extern __shared__ char smem[];
    uint32_t sbase = smem_u32(smem);
    int tid = threadIdx.x;
    int wid = tid >> 5, lane = tid & 31;
    int row0 = blockIdx.x * 128;
    const float* X = bufptr(in_sel);
    float* Y = bufptr(out_sel);

    // headers
    if (tid < 128) {
        int c = tid;
        float s = gamma[c] * rsqrtf(var[c] + BN_EPS);
        *(float*)(smem + c * 4) = s;
        *(float*)(smem + 512 + c * 4) = (b1[c] - mean[c]) * s + beta[c];
        *(float*)(smem + 1024 + c * 4) = b2[c];
    }

    // stage W1 + W2 images (flat copies)
    {
        const float4* s1 = (const float4*)(g_Wimg + (size_t)mat1 * WIMG_MAT);
        const float4* s2 = (const float4*)(g_Wimg + (size_t)mat2 * WIMG_MAT);
        float4* d1 = (float4*)(smem + B1_OFF);
        float4* d2 = (float4*)(smem + B2_OFF);
        for (int i = tid; i < WIMG_MAT / 16; i += 512) { d1[i] = s1[i]; d2[i] = s2[i]; }
    }

    // stage A: fp32 -> bf16 hi/lo planes (4 threads per row)
    {
        int r = tid >> 2, q = tid & 3;
        bool valid = (row0 + r) < N_NODES;
        const float4* xr = (const float4*)X + (size_t)(row0 + r) * 32 + q * 8;
        char* arow = smem + A_OFF + r * 272;
        #pragma unroll
        for (int p = 0; p < 8; p++) {
            float4 v = valid ? __ldg(&xr[p]) : make_float4(0.f, 0.f, 0.f, 0.f);
            int kb = (q * 32 + p * 4) * 2;
            __nv_bfloat16 hx = __float2bfloat16(v.x), hy = __float2bfloat16(v.y);
            __nv_bfloat16 hz = __float2bfloat16(v.z), hw = __float2bfloat16(v.w);
            __nv_bfloat162 h01; h01.x = hx; h01.y = hy;
            __nv_bfloat162 h23; h23.x = hz; h23.y = hw;
            __nv_bfloat162 l01, l23;
            l01.x = __float2bfloat16(v.x - __bfloat162float(hx));
            l01.y = __float2bfloat16(v.y - __bfloat162float(hy));
            l23.x = __float2bfloat16(v.z - __bfloat162float(hz));
            l23.y = __float2bfloat16(v.w - __bfloat162float(hw));
            *(uint32_t*)(arow + kb)     = *(uint32_t*)&h01;
            *(uint32_t*)(arow + kb + 4) = *(uint32_t*)&h23;
            *(uint32_t*)(arow + WIMG_PLANE + kb)     = *(uint32_t*)&l01;
            *(uint32_t*)(arow + WIMG_PLANE + kb + 4) = *(uint32_t*)&l23;
        }
    }
    __syncthreads();

    int wm = wid & 3, wn = wid >> 2;
    float acc[2][4][4];

    // ldmatrix lane base addresses (A region; B offsets added per GEMM)
    uint32_t addrA[2], addrBrel[2];
    #pragma unroll
    for (int mt = 0; mt < 2; mt++)
        addrA[mt] = sbase + A_OFF + (wm * 32 + mt * 16 + (lane & 15)) * 272
                    + (lane >> 4) * 16;
    #pragma unroll
    for (int ntp = 0; ntp < 2; ntp++) {
        int quad = lane >> 3;
        int n = wn * 32 + ntp * 16 + (quad >> 1) * 8 + (lane & 7);
        addrBrel[ntp] = n * 272 + (quad & 1) * 16;
    }

    // ---------- GEMM helper macro (3 passes of hi/lo split) ----------
    #define GEMM3(BOFFBASE)                                                        \
    {                                                                              \
        _Pragma("unroll")                                                          \
        for (int mt = 0; mt < 2; mt++)                                             \
            _Pragma("unroll")                                                      \
            for (int nt = 0; nt < 4; nt++)                                         \
                _Pragma("unroll")                                                  \
                for (int j = 0; j < 4; j++) acc[mt][nt][j] = 0.f;                  \
        _Pragma("unroll")                                                          \
        for (int pass = 0; pass < 3; pass++) {                                     \
            uint32_t aOff = (pass == 2) ? WIMG_PLANE : 0;                          \
            uint32_t bOff = (BOFFBASE) + ((pass == 1) ? WIMG_PLANE : 0);           \
            _Pragma("unroll")                                                      \
            for (int ks = 0; ks < 8; ks++) {                                       \
                uint32_t ko = ks * 32;                                             \
                uint32_t afr[2][4], bfr[2][4];                                     \
                _Pragma("unroll")                                                  \
                for (int mt = 0; mt < 2; mt++) ldsm4(addrA[mt] + aOff + ko, afr[mt]); \
                _Pragma("unroll")                                                  \
                for (int ntp = 0; ntp < 2; ntp++)                                  \
                    ldsm4(sbase + addrBrel[ntp] + bOff + ko, bfr[ntp]);            \
                _Pragma("unroll")                                                  \
                for (int mt = 0; mt < 2; mt++)                                     \
                    _Pragma("unroll")                                              \
                    for (int nt = 0; nt < 4; nt++)                                 \
                        mma16816(acc[mt][nt], afr[mt],                             \
                                 bfr[nt >> 1][(nt & 1) * 2],                       \
                                 bfr[nt >> 1][(nt & 1) * 2 + 1]);                  \
            }                                                                      \
        }                                                                          \
    }

    // GEMM1
    GEMM3(B1_OFF);
    __syncthreads();   // everyone done reading A planes before Z overwrites them

    // epilogue1: BN+ReLU, re-split into Z planes (overwriting A region)
    {
        char* base = smem + A_OFF;
        #pragma unroll
        for (int mt = 0; mt < 2; mt++) {
            #pragma unroll
            for (int nt = 0; nt < 4; nt++) {
                int n = wn * 32 + nt * 8 + (lane & 3) * 2;
                float2 sc = *(float2*)(smem + n * 4);
                float2 sh = *(float2*)(smem + 512 + n * 4);
                int lr1 = wm * 32 + mt * 16 + (lane >> 2);
                int lr2 = lr1 + 8;
                float* c = acc[mt][nt];
                float z0 = fmaxf(fmaf(c[0], sc.x, sh.x), 0.f);
                float z1 = fmaxf(fmaf(c[1], sc.y, sh.y), 0.f);
                float z2 = fmaxf(fmaf(c[2], sc.x, sh.x), 0.f);
                float z3 = fmaxf(fmaf(c[3], sc.y, sh.y), 0.f);
                __nv_bfloat16 h0 = __float2bfloat16(z0), h1 = __float2bfloat16(z1);
                __nv_bfloat16 h2 = __float2bfloat16(z2), h3 = __float2bfloat16(z3);
                *(uint32_t*)(base + lr1 * 272 + n * 2) = bf16pack(z0, z1);
                *(uint32_t*)(base + WIMG_PLANE + lr1 * 272 + n * 2) =
                    bf16pack(z0 - __bfloat162float(h0), z1 - __bfloat162float(h1));
                *(uint32_t*)(base + lr2 * 272 + n * 2) = bf16pack(z2, z3);
                *(uint32_t*)(base + WIMG_PLANE + lr2 * 272 + n * 2) =
                    bf16pack(z2 - __bfloat162float(h2), z3 - __bfloat162float(h3));
            }
        }
    }
    __syncthreads();

    // GEMM2
    GEMM3(B2_OFF);

    // epilogue2: bias+ReLU -> Y fp32 (+ fp16 shadow)
    #pragma unroll
    for (int mt = 0; mt < 2; mt++) {
        #pragma unroll
        for (int nt = 0; nt < 4; nt++) {
            int n = wn * 32 + nt * 8 + (lane & 3) * 2;
            float2 sh = *(float2*)(smem + 1024 + n * 4);
            int r1 = row0 + wm * 32 + mt * 16 + (lane >> 2);
            int r2 = r1 + 8;
            float* c = acc[mt][nt];
            if (r1 < N_NODES) {
                float2 o;
                o.x = fmaxf(c[0] + sh.x, 0.f);
                o.y = fmaxf(c[1] + sh.y, 0.f);
                *(float2*)(Y + (size_t)r1 * DIM + n) = o;
                if (write_half) g_bufH[(size_t)r1 * 64 + (n >> 1)] = __floats2half2_rn(o.x, o.y);
            }
            if (r2 < N_NODES) {
                float2 o;
                o.x = fmaxf(c[2] + sh.x, 0.f);
                o.y = fmaxf(c[3] + sh.y, 0.f);
                *(float2*)(Y + (size_t)r2 * DIM + n) = o;
                if (write_half) g_bufH[(size_t)r2 * 64 + (n >> 1)] = __floats2half2_rn(o.x, o.y);
            }
        }
    }
    #undef GEMM3
}

// ---------------- log-softmax (warp per row) ----------------
__global__ void k_lsm(int in_sel, float* __restrict__ Y) {
    int warp = (blockIdx.x * blockDim.x + threadIdx.x) >> 5;
    if (warp >= N_NODES) return;
    int lane = threadIdx.x & 31;
    const float* X = bufptr(in_sel);
    float4 v = ((const float4*)X)[(size_t)warp * 32 + lane];
    float m = fmaxf(fmaxf(v.x, v.y), fmaxf(v.z, v.w));
    #pragma unroll
    for (int o = 16; o; o >>= 1) m = fmaxf(m, __shfl_xor_sync(0xffffffffu, m, o));
    float s = expf(v.x - m) + expf(v.y - m) + expf(v.z - m) + expf(v.w - m);
    #pragma unroll
    for (int o = 16; o; o >>= 1) s += __shfl_xor_sync(0xffffffffu, s, o);
    float ls = m + logf(s);
    ((float4*)Y)[(size_t)warp * 32 + lane] =
        make_float4(v.x - ls, v.y - ls, v.z - ls, v.w - ls);
}

// ---------------- launch ----------------
extern "C" void kernel_launch(void* const* d_in, const int* in_sizes, int n_in,
                              void* d_out, int out_size) {
    const float* x     = (const float*)d_in[0];
    const void* ei     = d_in[1];
    const float* W1    = (const float*)d_in[2];
    const float* b1    = (const float*)d_in[3];
    const float* gamma = (const float*)d_in[4];
    const float* beta  = (const float*)d_in[5];
    const float* rmean = (const float*)d_in[6];
    const float* rvar  = (const float*)d_in[7];
    const float* W2    = (const float*)d_in[8];
    const float* b2    = (const float*)d_in[9];
    float* out = (float*)d_out;

    cudaFuncSetAttribute(k_mlp_fused, cudaFuncAttributeMaxDynamicSharedMemorySize, TC_SMEM);

    // CSR build + weight images + fp16 shadow of x
    k_detect<<<1, 1024>>>((const int*)ei);
    k_zero<<<(N_NODES + 255) / 256, 256>>>();
    k_wimg<<<(6 * 128 * 64 + 255) / 256, 256>>>(W1, W2);
    k_tohalf<<<(N_NODES * 32 + 255) / 256, 256>>>(x);
    k_hist<<<(N_EDGES + 255) / 256, 256>>>(ei);
    k_scanA<<<98, 1024>>>();
    k_scanB<<<1, 128>>>();
    k_scanC<<<98, 1024>>>();
    k_scatter<<<(N_EDGES + 255) / 256, 256>>>(ei);

    const int AGG_BLOCKS = (N_NODES * 32 + 255) / 256;
    const int MLP_BLOCKS = (N_NODES + 127) / 128;

    // dataflow: agg -> buf0 ; fused MLP: buf0 -> buf1 (+ g_bufH) ; repeat; lsm(buf1)
    int cur = -1;  // self-term source: x
    for (int l = 0; l < N_LAYERS; l++) {
        k_agg<<<AGG_BLOCKS, 256>>>(x, cur, 0);
        k_mlp_fused<<<MLP_BLOCKS, 512, TC_SMEM>>>(0, 1, l * 2, l * 2 + 1,
                                                  (l < N_LAYERS - 1) ? 1 : 0,
                                                  b1 + l * DIM, gamma + l * DIM,
                                                  beta + l * DIM, rmean + l * DIM,
                                                  rvar + l * DIM, b2 + l * DIM);
        cur = 1;
    }
    k_lsm<<<AGG_BLOCKS, 256>>>(1, out);
}